// round 5
// baseline (speedup 1.0000x reference)
#include <cuda_runtime.h>

// Output layout: x_hat (64*1*256*256) | ze (64*64*64*64) | zq (64*64*64*64)
#define OFF_ZE 4194304
#define OFF_ZQ 20971520

// Scratch (__device__ globals)
__device__ float g_h1[33554432];   // (64,32,128,128)
__device__ float g_h2[16777216];   // (64,64,64,64)
__device__ float g_dec[16777216];  // (64,64,64,64)
__device__ float g_d1[8388608];    // (64,32,64,64)
__device__ float g_d2[67108864];   // (64,64,128,128)

// ===========================================================================
// ENCODER — bit-exact emulation of XLA-CPU/Eigen conv:
// per output: acc = 0; sequential fused-FMA over (ky asc, kx asc, ci asc
// fastest); then y = max(add(acc, bias), 0). Zero-pad taps are exact no-ops.
// ===========================================================================

// e1: conv 1->32, k4 s2 p1. x(64,1,256,256) -> g_h1(64,32,128,128)
__global__ __launch_bounds__(256) void k_e1(const float* __restrict__ x,
                                            const float* __restrict__ w,
                                            const float* __restrict__ b) {
    __shared__ float sw[16][32];   // [tap][o]
    __shared__ float sb[32];
    int t = threadIdx.x;
    {
        int o = t & 31, tap = t >> 5;
        sw[tap][o] = w[o * 16 + tap];
        int e = t + 256; o = e & 31; tap = e >> 5;
        sw[tap][o] = w[o * 16 + tap];
    }
    if (t < 32) sb[t] = b[t];
    __syncthreads();
    int gid = blockIdx.x * 256 + t;
    int ox = gid & 127, oy = (gid >> 7) & 127, n = gid >> 14;
    float acc[32];
#pragma unroll
    for (int o = 0; o < 32; o++) acc[o] = 0.f;
    const float* xin = x + n * 65536;
#pragma unroll
    for (int ky = 0; ky < 4; ky++) {
        int iy = 2 * oy - 1 + ky;
        if (iy < 0 || iy >= 256) continue;
#pragma unroll
        for (int kx = 0; kx < 4; kx++) {
            int ix = 2 * ox - 1 + kx;
            if (ix < 0 || ix >= 256) continue;
            float v = xin[iy * 256 + ix];
#pragma unroll
            for (int o = 0; o < 32; o++) acc[o] = fmaf(v, sw[ky * 4 + kx][o], acc[o]);
        }
    }
    float* op = g_h1 + n * 524288 + oy * 128 + ox;
#pragma unroll
    for (int o = 0; o < 32; o++) op[o * 16384] = fmaxf(__fadd_rn(acc[o], sb[o]), 0.f);
}

// e2: conv 32->64, k4 s2 p1. g_h1 -> g_h2(64,64,64,64)
// 256 thr: 8 oc-groups x (16 rows x 2 x-halves). Thread: 8 spatial x 8 oc.
// Weights ky-chunked (order-safe: ky is outermost in the chain).
#define E2_PITCH 35
#define E2_IN_FLOATS (32 * 34 * E2_PITCH)     // 38080
#define E2_W_FLOATS  (4 * 32 * 64)            // 8192
#define E2_SMEM_B   ((E2_IN_FLOATS + E2_W_FLOATS) * 4)
__global__ __launch_bounds__(256, 1) void k_e2(const float* __restrict__ w,
                                               const float* __restrict__ b) {
    extern __shared__ float sm[];
    float* sIn = sm;                 // [ci][34][35]
    float* sw  = sm + E2_IN_FLOATS;  // [kx][ci][o]
    int tid = threadIdx.x;
    int og8 = tid >> 5;
    int sp = tid & 31;
    int r = sp >> 1, h = sp & 1;
    int t_y = blockIdx.x >> 2, t_x = blockIdx.x & 3;
    int n = blockIdx.y;
    int iy0 = 32 * t_y - 1, ix0 = 32 * t_x - 1;
    for (int idx = tid; idx < 32 * 34 * 34; idx += 256) {
        int ci = idx / 1156, rr = idx - ci * 1156;
        int iy = rr / 34, ix = rr - iy * 34;
        int gy = iy0 + iy, gx = ix0 + ix;
        float v = 0.f;
        if (gy >= 0 && gy < 128 && gx >= 0 && gx < 128)
            v = g_h1[((n * 32 + ci) * 128 + gy) * 128 + gx];
        sIn[ci * (34 * E2_PITCH) + iy * E2_PITCH + ix] = v;
    }
    float acc[64];
#pragma unroll
    for (int i = 0; i < 64; i++) acc[i] = 0.f;
#pragma unroll
    for (int ky = 0; ky < 4; ky++) {
        __syncthreads();
        for (int idx = tid; idx < E2_W_FLOATS; idx += 256) {
            int kx = idx >> 11, ci = (idx >> 6) & 31, o = idx & 63;
            sw[idx] = w[(o * 32 + ci) * 16 + ky * 4 + kx];
        }
        __syncthreads();
#pragma unroll
        for (int kx = 0; kx < 4; kx++) {
            for (int ci = 0; ci < 32; ci++) {
                const float* vb = &sIn[ci * (34 * E2_PITCH) + (2 * r + ky) * E2_PITCH + 16 * h + kx];
                float v[8];
#pragma unroll
                for (int j = 0; j < 8; j++) v[j] = vb[2 * j];
                const float4* wp = (const float4*)&sw[(kx * 32 + ci) * 64 + og8 * 8];
                float4 w0 = wp[0], w1 = wp[1];
                float wv[8] = {w0.x, w0.y, w0.z, w0.w, w1.x, w1.y, w1.z, w1.w};
#pragma unroll
                for (int j = 0; j < 8; j++)
#pragma unroll
                    for (int oo = 0; oo < 8; oo++)
                        acc[j * 8 + oo] = fmaf(v[j], wv[oo], acc[j * 8 + oo]);
            }
        }
    }
    int oy = 16 * t_y + r, ox0 = 16 * t_x + 8 * h;
#pragma unroll
    for (int oo = 0; oo < 8; oo++) {
        int o = og8 * 8 + oo;
        float bb = b[o];
        float* op = g_h2 + ((n * 64 + o) * 64 + oy) * 64 + ox0;
#pragma unroll
        for (int j = 0; j < 8; j++)
            op[j] = fmaxf(__fadd_rn(acc[j * 8 + oo], bb), 0.f);
    }
}

// e3: conv 64->64, k3 s1 p1. g_h2 -> ze (d_out)
#define E3_PITCH 21
#define E3_IN_FLOATS (64 * 18 * E3_PITCH)    // 24192
#define E3_W_FLOATS  (3 * 64 * 64)           // 12288
#define E3_SMEM_B   ((E3_IN_FLOATS + E3_W_FLOATS) * 4)
__global__ __launch_bounds__(256, 1) void k_e3(const float* __restrict__ w,
                                               const float* __restrict__ b,
                                               float* __restrict__ ze) {
    extern __shared__ float sm[];
    float* sIn = sm;                 // [ci][18][21]
    float* sw  = sm + E3_IN_FLOATS;  // [kx][ci][o]
    int tid = threadIdx.x;
    int og8 = tid >> 5;
    int sp = tid & 31;
    int r = sp >> 1, h = sp & 1;
    int t_y = blockIdx.x >> 2, t_x = blockIdx.x & 3;
    int n = blockIdx.y;
    int iy0 = 16 * t_y - 1, ix0 = 16 * t_x - 1;
    for (int idx = tid; idx < 64 * 18 * 18; idx += 256) {
        int ci = idx / 324, rr = idx - ci * 324;
        int iy = rr / 18, ix = rr - iy * 18;
        int gy = iy0 + iy, gx = ix0 + ix;
        float v = 0.f;
        if (gy >= 0 && gy < 64 && gx >= 0 && gx < 64)
            v = g_h2[((n * 64 + ci) * 64 + gy) * 64 + gx];
        sIn[ci * (18 * E3_PITCH) + iy * E3_PITCH + ix] = v;
    }
    float acc[64];
#pragma unroll
    for (int i = 0; i < 64; i++) acc[i] = 0.f;
#pragma unroll
    for (int ky = 0; ky < 3; ky++) {
        __syncthreads();
        for (int idx = tid; idx < E3_W_FLOATS; idx += 256) {
            int kx = idx >> 12, ci = (idx >> 6) & 63, o = idx & 63;
            sw[idx] = w[(o * 64 + ci) * 9 + ky * 3 + kx];
        }
        __syncthreads();
#pragma unroll
        for (int kx = 0; kx < 3; kx++) {
            for (int ci = 0; ci < 64; ci++) {
                const float* vb = &sIn[ci * (18 * E3_PITCH) + (r + ky) * E3_PITCH + 8 * h + kx];
                float v[8];
#pragma unroll
                for (int j = 0; j < 8; j++) v[j] = vb[j];
                const float4* wp = (const float4*)&sw[(kx * 64 + ci) * 64 + og8 * 8];
                float4 w0 = wp[0], w1 = wp[1];
                float wv[8] = {w0.x, w0.y, w0.z, w0.w, w1.x, w1.y, w1.z, w1.w};
#pragma unroll
                for (int j = 0; j < 8; j++)
#pragma unroll
                    for (int oo = 0; oo < 8; oo++)
                        acc[j * 8 + oo] = fmaf(v[j], wv[oo], acc[j * 8 + oo]);
            }
        }
    }
    int oy = 16 * t_y + r, ox0 = 16 * t_x + 8 * h;
#pragma unroll
    for (int oo = 0; oo < 8; oo++) {
        int o = og8 * 8 + oo;
        float bb = b[o];
        float* op = ze + ((n * 64 + o) * 64 + oy) * 64 + ox0;
#pragma unroll
        for (int j = 0; j < 8; j++)
            op[j] = fmaxf(__fadd_rn(acc[j * 8 + oo], bb), 0.f);
    }
}

// ===========================================================================
// VQ — exact f32 replica of reference arithmetic:
//   sqz  = seq c: add(sqz, mul(z,z))            (XLA reduce, unfused)
//   dot  = seq c: fmaf(z, e, dot)               (Eigen gemm)
//   sqe  = seq c: add(sqe, mul(e,e))
//   dist = add(sub(sqz, mul(2, dot)), sqe)
//   argmin ascending k, strict < (first min wins)
// Codebook transposed in smem: [c][k] so 4 chains share one LDS128.
// ===========================================================================
#define VQ_SMEM_B ((64 * 512 + 512) * 4)
__global__ __launch_bounds__(256) void k_vq(const float* __restrict__ ze,
                                            const float* __restrict__ emb,
                                            float* __restrict__ zq) {
    extern __shared__ float sm[];
    float* se = sm;           // [c][k] = 64 x 512
    float* sn = sm + 32768;   // sqe[k]
    int tid = threadIdx.x;
    for (int i = tid; i < 32768; i += 256) {
        int k = i >> 6, c = i & 63;
        se[c * 512 + k] = emb[i];
    }
    __syncthreads();
    for (int k = tid; k < 512; k += 256) {
        float s = 0.f;
#pragma unroll
        for (int c = 0; c < 64; c++) {
            float e = se[c * 512 + k];
            s = __fadd_rn(s, __fmul_rn(e, e));
        }
        sn[k] = s;
    }
    __syncthreads();
    int gid = blockIdx.x * 256 + tid;
    int x = gid & 63, y = (gid >> 6) & 63, n = gid >> 12;
    const float* zp = ze + n * 262144 + y * 64 + x;
    float z[64];
#pragma unroll
    for (int c = 0; c < 64; c++) z[c] = zp[c * 4096];
    float sqz = 0.f;
#pragma unroll
    for (int c = 0; c < 64; c++) sqz = __fadd_rn(sqz, __fmul_rn(z[c], z[c]));
    float best = 3.4028235e38f;
    int bi = 0;
    for (int k0 = 0; k0 < 512; k0 += 4) {
        float d0 = 0.f, d1 = 0.f, d2 = 0.f, d3 = 0.f;
#pragma unroll
        for (int c = 0; c < 64; c++) {
            float4 e = *(const float4*)&se[c * 512 + k0];
            d0 = fmaf(z[c], e.x, d0);
            d1 = fmaf(z[c], e.y, d1);
            d2 = fmaf(z[c], e.z, d2);
            d3 = fmaf(z[c], e.w, d3);
        }
        float q0 = __fadd_rn(__fsub_rn(sqz, __fmul_rn(2.f, d0)), sn[k0]);
        float q1 = __fadd_rn(__fsub_rn(sqz, __fmul_rn(2.f, d1)), sn[k0 + 1]);
        float q2 = __fadd_rn(__fsub_rn(sqz, __fmul_rn(2.f, d2)), sn[k0 + 2]);
        float q3 = __fadd_rn(__fsub_rn(sqz, __fmul_rn(2.f, d3)), sn[k0 + 3]);
        if (q0 < best) { best = q0; bi = k0; }
        if (q1 < best) { best = q1; bi = k0 + 1; }
        if (q2 < best) { best = q2; bi = k0 + 2; }
        if (q3 < best) { best = q3; bi = k0 + 3; }
    }
    float* zqp = zq + n * 262144 + y * 64 + x;
    float* dp = g_dec + n * 262144 + y * 64 + x;
#pragma unroll
    for (int c = 0; c < 64; c++) {
        float e = se[c * 512 + bi];
        zqp[c * 4096] = e;
        dp[c * 4096] = __fadd_rn(z[c], __fsub_rn(e, z[c]));  // ze + (zq - ze)
    }
}

// ===========================================================================
// DECODER (1e-3 tolerance: fast kernels, order-free)
// ===========================================================================

// d1: conv_t 64->32, k3 s1 p1 == conv with flipped/swapped weights
__global__ __launch_bounds__(256) void k_d1(const float* __restrict__ w,
                                            const float* __restrict__ b) {
    __shared__ float sIn[8 * 324];
    __shared__ float sw[2304];
    int tid = threadIdx.x;
    int sy = tid >> 4, sx = tid & 15;
    int tb = blockIdx.x;
    int tx = tb & 3, ty = tb >> 2;
    int n = blockIdx.y;
    int iy0 = 16 * ty - 1, ix0 = 16 * tx - 1;
    float acc[32];
#pragma unroll
    for (int o = 0; o < 32; o++) acc[o] = b[o];
    for (int cc = 0; cc < 8; cc++) {
        __syncthreads();
        for (int e = tid; e < 2592; e += 256) {
            int ci = e / 324, r = e - ci * 324;
            int iy = r / 18, ix = r - iy * 18;
            int gy = iy0 + iy, gx = ix0 + ix;
            float v = 0.f;
            if (gy >= 0 && gy < 64 && gx >= 0 && gx < 64)
                v = g_dec[((n * 64 + cc * 8 + ci) * 64 + gy) * 64 + gx];
            sIn[e] = v;
        }
        for (int e = tid; e < 2304; e += 256) {
            int ci = e / 288, r = e - ci * 288;
            int kk = r >> 5, o = r & 31;
            sw[e] = w[((cc * 8 + ci) * 32 + o) * 9 + (8 - kk)];
        }
        __syncthreads();
#pragma unroll
        for (int ci = 0; ci < 8; ci++) {
#pragma unroll
            for (int ky = 0; ky < 3; ky++) {
                const float* ip = &sIn[ci * 324 + (sy + ky) * 18 + sx];
#pragma unroll
                for (int kx = 0; kx < 3; kx++) {
                    float v = ip[kx];
                    const float* wp = &sw[(ci * 9 + ky * 3 + kx) * 32];
#pragma unroll
                    for (int o = 0; o < 32; o++) acc[o] = fmaf(v, wp[o], acc[o]);
                }
            }
        }
    }
    int oy = 16 * ty + sy, ox = 16 * tx + sx;
    float* op = g_d1 + n * 131072 + oy * 64 + ox;
#pragma unroll
    for (int o = 0; o < 32; o++) op[o * 4096] = fmaxf(acc[o], 0.f);
}

// d2: conv_t 32->64, k4 s2 p1
__global__ __launch_bounds__(512, 1) void k_d2(const float* __restrict__ w,
                                               const float* __restrict__ b) {
    __shared__ float sIn[3200];
    __shared__ float sw[8192];
    int tid = threadIdx.x;
    int og = tid >> 8;
    int s = tid & 255;
    int sy = s >> 4, sx = s & 15;
    int tb = blockIdx.x;
    int tx = tb & 7, ty = tb >> 3;
    int n = blockIdx.y;
    int iy0 = 8 * ty - 1, ix0 = 8 * tx - 1;
    for (int e = tid; e < 3200; e += 512) {
        int ci = e / 100, r = e - ci * 100;
        int iy = r / 10, ix = r - iy * 10;
        int gy = iy0 + iy, gx = ix0 + ix;
        float v = 0.f;
        if (gy >= 0 && gy < 64 && gx >= 0 && gx < 64)
            v = g_d1[((n * 32 + ci) * 64 + gy) * 64 + gx];
        sIn[e] = v;
    }
    float acc[32];
#pragma unroll
    for (int o = 0; o < 32; o++) acc[o] = b[og * 32 + o];
    int y = 16 * ty + sy, x = 16 * tx + sx;
    int py = (y + 1) & 1, px = (x + 1) & 1;
    int iya = ((sy + 1 - py) >> 1) + 1, ixa = ((sx + 1 - px) >> 1) + 1;
    for (int cc = 0; cc < 4; cc++) {
        __syncthreads();
        for (int e = tid; e < 8192; e += 512) {
            int ci = e >> 10, kk = (e >> 6) & 15, o = e & 63;
            sw[e] = w[((cc * 8 + ci) * 64 + o) * 16 + kk];
        }
        __syncthreads();
#pragma unroll
        for (int ci = 0; ci < 8; ci++) {
#pragma unroll
            for (int t_y = 0; t_y < 2; t_y++) {
                int ky = py + 2 * t_y, iyl = iya - t_y;
#pragma unroll
                for (int t_x = 0; t_x < 2; t_x++) {
                    int kx = px + 2 * t_x, ixl = ixa - t_x;
                    float v = sIn[(cc * 8 + ci) * 100 + iyl * 10 + ixl];
                    const float* wp = &sw[(ci * 16 + ky * 4 + kx) * 64 + og * 32];
#pragma unroll
                    for (int o = 0; o < 32; o++) acc[o] = fmaf(v, wp[o], acc[o]);
                }
            }
        }
    }
    float* op = g_d2 + n * 1048576 + (og * 32) * 16384 + y * 128 + x;
#pragma unroll
    for (int o = 0; o < 32; o++) op[o * 16384] = fmaxf(acc[o], 0.f);
}

// d3: conv_t 64->1, k4 s2 p1 -> x_hat
__global__ __launch_bounds__(256) void k_d3(const float* __restrict__ w,
                                            const float* __restrict__ b,
                                            float* __restrict__ xh) {
    __shared__ float sIn[6400];
    __shared__ float sw[1024];
    int tid = threadIdx.x;
    int sy = tid >> 4, sx = tid & 15;
    int tb = blockIdx.x;
    int tx = tb & 15, ty = tb >> 4;
    int n = blockIdx.y;
    int iy0 = 8 * ty - 1, ix0 = 8 * tx - 1;
    for (int e = tid; e < 6400; e += 256) {
        int ci = e / 100, r = e - ci * 100;
        int iy = r / 10, ix = r - iy * 10;
        int gy = iy0 + iy, gx = ix0 + ix;
        float v = 0.f;
        if (gy >= 0 && gy < 128 && gx >= 0 && gx < 128)
            v = g_d2[((n * 64 + ci) * 128 + gy) * 128 + gx];
        sIn[e] = v;
    }
    for (int e = tid; e < 1024; e += 256) sw[e] = w[e];
    __syncthreads();
    int y = 16 * ty + sy, x = 16 * tx + sx;
    int py = (y + 1) & 1, px = (x + 1) & 1;
    int iya = ((sy + 1 - py) >> 1) + 1, ixa = ((sx + 1 - px) >> 1) + 1;
    float acc = b[0];
#pragma unroll 8
    for (int ci = 0; ci < 64; ci++) {
#pragma unroll
        for (int t_y = 0; t_y < 2; t_y++) {
            int ky = py + 2 * t_y, iyl = iya - t_y;
#pragma unroll
            for (int t_x = 0; t_x < 2; t_x++) {
                int kx = px + 2 * t_x, ixl = ixa - t_x;
                acc = fmaf(sIn[ci * 100 + iyl * 10 + ixl], sw[ci * 16 + ky * 4 + kx], acc);
            }
        }
    }
    xh[n * 65536 + y * 256 + x] = acc;
}

// ---------------------------------------------------------------------------
extern "C" void kernel_launch(void* const* d_in, const int* in_sizes, int n_in,
                              void* d_out, int out_size) {
    const float* x   = (const float*)d_in[0];
    const float* e1w = (const float*)d_in[1];
    const float* e1b = (const float*)d_in[2];
    const float* e2w = (const float*)d_in[3];
    const float* e2b = (const float*)d_in[4];
    const float* e3w = (const float*)d_in[5];
    const float* e3b = (const float*)d_in[6];
    const float* emb = (const float*)d_in[7];
    const float* d1w = (const float*)d_in[8];
    const float* d1b = (const float*)d_in[9];
    const float* d2w = (const float*)d_in[10];
    const float* d2b = (const float*)d_in[11];
    const float* d3w = (const float*)d_in[12];
    const float* d3b = (const float*)d_in[13];
    float* out = (float*)d_out;
    float* ze = out + OFF_ZE;
    float* zq = out + OFF_ZQ;

    cudaFuncSetAttribute(k_e2, cudaFuncAttributeMaxDynamicSharedMemorySize, E2_SMEM_B);
    cudaFuncSetAttribute(k_e3, cudaFuncAttributeMaxDynamicSharedMemorySize, E3_SMEM_B);
    cudaFuncSetAttribute(k_vq, cudaFuncAttributeMaxDynamicSharedMemorySize, VQ_SMEM_B);

    k_e1<<<4096, 256>>>(x, e1w, e1b);
    k_e2<<<dim3(16, 64), 256, E2_SMEM_B>>>(e2w, e2b);
    k_e3<<<dim3(16, 64), 256, E3_SMEM_B>>>(e3w, e3b, ze);
    k_vq<<<1024, 256, VQ_SMEM_B>>>(ze, emb, zq);
    k_d1<<<dim3(16, 64), 256>>>(d1w, d1b);
    k_d2<<<dim3(64, 64), 512>>>(d2w, d2b);
    k_d3<<<dim3(256, 64), 256>>>(d3w, d3b, out);
}